// round 16
// baseline (speedup 1.0000x reference)
#include <cuda_runtime.h>
#include <cstdint>
#include <cstddef>

#define NN   1024
#define DIMX 384
#define HN   8
#define PDW  128
#define OUTW 1152   // H*DV + H*PD = 128 + 1024

static constexpr float SCALAR_SCALE = 0.14433756729740643f; // (3*16)^-0.5
static constexpr float PAIR_SCALE   = 0.5773502691896258f;  // 3^-0.5

// Scratch (static __device__ — no allocations allowed)
static __device__ float g_q[NN * 128];
static __device__ float g_k[NN * 128];
static __device__ float g_v[NN * 128];

typedef unsigned long long u64;

__device__ __forceinline__ u64 pack2(float lo, float hi) {
    u64 r; asm("mov.b64 %0, {%1, %2};" : "=l"(r) : "f"(lo), "f"(hi)); return r;
}
__device__ __forceinline__ void unpack2(u64 v, float& lo, float& hi) {
    asm("mov.b64 {%0, %1}, %2;" : "=f"(lo), "=f"(hi) : "l"(v));
}
__device__ __forceinline__ u64 ffma2(u64 a, u64 b, u64 c) {
    u64 r; asm("fma.rn.f32x2 %0, %1, %2, %3;" : "=l"(r) : "l"(a), "l"(b), "l"(c)); return r;
}
__device__ __forceinline__ uint32_t smem_u32(const void* p) {
    return (uint32_t)__cvta_generic_to_shared(p);
}
__device__ __forceinline__ void cp16_cg(uint32_t dst, const void* src) {
    asm volatile("cp.async.cg.shared.global [%0], [%1], 16;" :: "r"(dst), "l"(src));
}
#define CP_COMMIT() asm volatile("cp.async.commit_group;" ::: "memory")
#define CP_WAIT(N)  asm volatile("cp.async.wait_group %0;" :: "n"(N) : "memory")

// fused smem layout (bytes): pr ring (8 warps x 8 slots x 512B) + partials
#define FR_SLOT   512
#define FR_NSLOT  8
#define FR_DEPTH  7                          // rows in flight
#define FR_RINGW  (FR_NSLOT * FR_SLOT)       // 4 KB / warp
#define FR_RING   (8 * FR_RINGW)             // 32 KB
#define FR_MB     (8 * 1160 * 4)             // 37120 B
#define FR_SMEM   (FR_RING + FR_MB + 64)     // 69952 B -> 2 CTAs = 139.9 KB/SM

// ---------------------------------------------------------------------------
// Kernel A: q/k/v projections. grid (64, 3), block 256 (8 warps).
// Warp = 8 rows x 32 cols: W slice/warp = 49 KB -> total W L2 traffic 75 MB.
// ---------------------------------------------------------------------------
__global__ void __launch_bounds__(256) proj_kernel(
    const float* __restrict__ x,
    const float* __restrict__ Wq,
    const float* __restrict__ Wk,
    const float* __restrict__ Wv)
{
    __shared__ float xs[16 * DIMX];   // 24 KB
    const int rb = blockIdx.x * 16;
    const float* W   = (blockIdx.y == 0) ? Wq  : (blockIdx.y == 1) ? Wk  : Wv;
    float*       dst = (blockIdx.y == 0) ? g_q : (blockIdx.y == 1) ? g_k : g_v;
    const float scale = (blockIdx.y == 0) ? SCALAR_SCALE : 1.0f;

    for (int t = threadIdx.x; t < 16 * DIMX; t += 256)
        xs[t] = x[(size_t)rb * DIMX + t];
    __syncthreads();

    const int wid  = threadIdx.x >> 5;
    const int lane = threadIdx.x & 31;
    const int rg   = wid >> 2;
    const int cg   = wid & 3;
    const int c    = cg * 32 + lane;
    const int r0   = rg * 8;

    float acc[8];
#pragma unroll
    for (int r = 0; r < 8; r++) acc[r] = 0.0f;

    float wbuf[4];
#pragma unroll
    for (int u = 0; u < 4; u++)
        wbuf[u] = __ldg(&W[u * 128 + c]);

#pragma unroll 1
    for (int k0 = 0; k0 < DIMX; k0 += 4) {
        float wcur[4];
#pragma unroll
        for (int u = 0; u < 4; u++) wcur[u] = wbuf[u];
        const int kn = (k0 + 4 < DIMX) ? (k0 + 4) : 0;   // clamp: valid addr
#pragma unroll
        for (int u = 0; u < 4; u++)
            wbuf[u] = __ldg(&W[(kn + u) * 128 + c]);
#pragma unroll
        for (int u = 0; u < 4; u++) {
#pragma unroll
            for (int r = 0; r < 8; r++)
                acc[r] = fmaf(xs[(r0 + r) * DIMX + k0 + u], wcur[u], acc[r]);
        }
    }
#pragma unroll
    for (int r = 0; r < 8; r++)
        dst[(size_t)(rb + r0 + r) * 128 + c] = acc[r] * scale;
}

// ---------------------------------------------------------------------------
// Kernel B: FULLY FUSED single pass (v4 = v3 + 8-slot ring). grid 1024
// (CTA = query i), block 256 (8 warps; warp = 128 consecutive j).
// 2 CTAs/SM -> 16 warps/SM. Lane = (h = lane&7, q = lane>>3).
//
// v4 change: pr ring deepened 4 -> 8 slots (7 rows in flight, CP_WAIT(6)).
// Hidden latency = 7 x T_iter ~ 700 cyc >= DRAM latency; the R15 profile
// showed CP_WAIT(2) exposing ~300-700 cyc/iteration (DRAM 18%, issue 25%).
// Zero register cost (staging lives in smem).
//
// Per j: 1 cp.async (pr row), 8 LDS.128 (pr -> regs ONCE, conflict-free
// 8-way broadcast), 2 __ldg (k/v slices, L1-resident), lane-local dot,
// xor8/16 fold, exp, accp/accv/l. ~124 regs, no spill.
// ---------------------------------------------------------------------------
__global__ void __launch_bounds__(256, 2) fused_kernel(
    const float* __restrict__ pair,
    const float* __restrict__ Wb,
    const float* __restrict__ bb,
    float* __restrict__ out)
{
    extern __shared__ char smem[];
    float* mb = (float*)(smem + FR_RING);    // 8 x 1160 partials
    float* rs = (float*)(smem + FR_RING + FR_MB);

    const int tid  = threadIdx.x;
    const int wid  = tid >> 5;
    const int lane = tid & 31;
    const int h    = lane & 7;
    const int q    = lane >> 3;

    const int i  = blockIdx.x;
    const int j0 = wid * 128;

    // Wb rows for this lane's d-set (chunks f = u*4+q), pre-scaled.
    u64 wb2[16];
#pragma unroll
    for (int u = 0; u < 8; u++) {
        const int d = (u * 4 + q) * 4;
        wb2[2 * u]     = pack2(Wb[(d + 0) * 8 + h] * PAIR_SCALE, Wb[(d + 1) * 8 + h] * PAIR_SCALE);
        wb2[2 * u + 1] = pack2(Wb[(d + 2) * 8 + h] * PAIR_SCALE, Wb[(d + 3) * 8 + h] * PAIR_SCALE);
    }
    const float4 qv = *(const float4*)&g_q[(size_t)i * 128 + h * 16 + q * 4];
    const float bbh = bb[h] * PAIR_SCALE;
    const int koff = h * 4 + q;      // float4 index of (h,q) slice in a row

    const float4* k4g = (const float4*)g_k;
    const float4* v4g = (const float4*)g_v;

    const char* prsrc = (const char*)pair + ((size_t)i * NN + j0) * 512;
    const int lb = lane * 16;
    const uint32_t ringw = smem_u32(smem) + wid * FR_RINGW;
    const char* ringp = smem + wid * FR_RINGW;

    u64 accp[16];
#pragma unroll
    for (int t = 0; t < 16; t++) accp[t] = 0ull;
    float4 accv = make_float4(0.f, 0.f, 0.f, 0.f);
    float l = 0.0f;

    // prologue: stage pr rows 0..6 (7 groups in flight)
#pragma unroll
    for (int t = 0; t < FR_DEPTH; t++) {
        cp16_cg(ringw + t * FR_SLOT + lb, prsrc + (size_t)t * 512 + lb);
        CP_COMMIT();
    }

#pragma unroll 1
    for (int t = 0; t < 128; t++) {
        // issue k/v loads first so their latency overlaps the LDS + dot
        const float4 kc = __ldg(k4g + (size_t)(j0 + t) * 32 + koff);
        const float4 vc = __ldg(v4g + (size_t)(j0 + t) * 32 + koff);

        CP_WAIT(6);                      // row t complete (6 newer groups pend)
        __syncwarp();

        const float4* sp = (const float4*)(ringp + (t & (FR_NSLOT - 1)) * FR_SLOT);

        // load pr chunks ONCE into registers (used for dot AND accp)
        u64 pr2[16];
#pragma unroll
        for (int u = 0; u < 8; u++) {
            const float4 c = sp[u * 4 + q];
            pr2[2 * u]     = pack2(c.x, c.y);
            pr2[2 * u + 1] = pack2(c.z, c.w);
        }

        // bias dot: two independent f32x2 chains
        u64 a0 = 0ull, a1 = 0ull;
#pragma unroll
        for (int u = 0; u < 8; u++) {
            a0 = ffma2(pr2[2 * u],     wb2[2 * u],     a0);
            a1 = ffma2(pr2[2 * u + 1], wb2[2 * u + 1], a1);
        }
        float d0, d1, d2, d3;
        unpack2(a0, d0, d1); unpack2(a1, d2, d3);

        float qk = qv.x * kc.x;
        qk = fmaf(qv.y, kc.y, qk);
        qk = fmaf(qv.z, kc.z, qk);
        qk = fmaf(qv.w, kc.w, qk);

        float dot = ((d0 + d1) + (d2 + d3)) + qk;
        dot += __shfl_xor_sync(0xffffffffu, dot, 8);
        dot += __shfl_xor_sync(0xffffffffu, dot, 16);

        const float p = __expf(dot + bbh);       // same on all 4 q-lanes of h
        l += p;
        const u64 ph = pack2(p, p);

#pragma unroll
        for (int u = 0; u < 16; u++) accp[u] = ffma2(ph, pr2[u], accp[u]);

        accv.x = fmaf(p, vc.x, accv.x);
        accv.y = fmaf(p, vc.y, accv.y);
        accv.z = fmaf(p, vc.z, accv.z);
        accv.w = fmaf(p, vc.w, accv.w);

        __syncwarp();                    // all lanes done reading slot

        // refill slot (t+7)&7 with row (t+7) (wrapped valid addr)
        const int tr = (t + FR_DEPTH) & 127;
        cp16_cg(ringw + ((t + FR_DEPTH) & (FR_NSLOT - 1)) * FR_SLOT + lb,
                prsrc + (size_t)tr * 512 + lb);
        CP_COMMIT();
    }
    CP_WAIT(0);

    // ---- epilogue: dump per-warp partials, reduce across 8 warps ----
    {
        float* m = mb + wid * 1160;
        *(float4*)&m[koff * 4] = accv;                    // v part: h*16 + q*4
#pragma unroll
        for (int u = 0; u < 8; u++) {
            float a0, a1, a2, a3;
            unpack2(accp[2 * u],     a0, a1);
            unpack2(accp[2 * u + 1], a2, a3);
            *(float4*)&m[128 + h * 128 + u * 16 + q * 4] = make_float4(a0, a1, a2, a3);
        }
        if (q == 0) m[1152 + h] = l;
    }
    __syncthreads();

    if (tid < 8) {
        float s = 0.0f;
#pragma unroll
        for (int w = 0; w < 8; w++) s += mb[w * 1160 + 1152 + tid];
        rs[tid] = 1.0f / s;
    }
    __syncthreads();

    const size_t ob = (size_t)i * OUTW;
    for (int idx = tid; idx < OUTW; idx += 256) {
        float s = 0.0f;
#pragma unroll
        for (int w = 0; w < 8; w++) s += mb[w * 1160 + idx];
        const int head = (idx < 128) ? (idx >> 4) : ((idx - 128) >> 7);
        out[ob + idx] = s * rs[head];
    }
}

// ---------------------------------------------------------------------------
extern "C" void kernel_launch(void* const* d_in, const int* in_sizes, int n_in,
                              void* d_out, int out_size)
{
    (void)in_sizes; (void)n_in; (void)out_size;
    const float* x    = (const float*)d_in[0];
    const float* pair = (const float*)d_in[1];
    // d_in[2]=rotations, d_in[3]=translations, d_in[4]=mask: unused by reference math
    const float* Wq = (const float*)d_in[5];
    const float* Wk = (const float*)d_in[6];
    const float* Wv = (const float*)d_in[7];
    const float* Wb = (const float*)d_in[8];
    const float* bb = (const float*)d_in[9];
    float* out = (float*)d_out;

    proj_kernel<<<dim3(64, 3, 1), 256>>>(x, Wq, Wk, Wv);

    cudaFuncSetAttribute(fused_kernel, cudaFuncAttributeMaxDynamicSharedMemorySize, FR_SMEM);
    fused_kernel<<<1024, 256, FR_SMEM>>>(pair, Wb, bb, out);
}

// round 17
// speedup vs baseline: 1.3066x; 1.3066x over previous
#include <cuda_runtime.h>
#include <cstdint>
#include <cstddef>

#define NN   1024
#define DIMX 384
#define HN   8
#define PDW  128
#define OUTW 1152   // H*DV + H*PD = 128 + 1024

static constexpr float SCALAR_SCALE = 0.14433756729740643f; // (3*16)^-0.5
static constexpr float PAIR_SCALE   = 0.5773502691896258f;  // 3^-0.5

// Scratch (static __device__ — no allocations allowed)
static __device__ float g_q[NN * 128];
static __device__ float g_k[NN * 128];
static __device__ float g_v[NN * 128];

typedef unsigned long long u64;

__device__ __forceinline__ u64 pack2(float lo, float hi) {
    u64 r; asm("mov.b64 %0, {%1, %2};" : "=l"(r) : "f"(lo), "f"(hi)); return r;
}
__device__ __forceinline__ void unpack2(u64 v, float& lo, float& hi) {
    asm("mov.b64 {%0, %1}, %2;" : "=f"(lo), "=f"(hi) : "l"(v));
}
__device__ __forceinline__ u64 ffma2(u64 a, u64 b, u64 c) {
    u64 r; asm("fma.rn.f32x2 %0, %1, %2, %3;" : "=l"(r) : "l"(a), "l"(b), "l"(c)); return r;
}
__device__ __forceinline__ uint32_t smem_u32(const void* p) {
    return (uint32_t)__cvta_generic_to_shared(p);
}
__device__ __forceinline__ void cp16_cg(uint32_t dst, const void* src) {
    asm volatile("cp.async.cg.shared.global [%0], [%1], 16;" :: "r"(dst), "l"(src));
}
#define CP_COMMIT() asm volatile("cp.async.commit_group;" ::: "memory")
#define CP_WAIT(N)  asm volatile("cp.async.wait_group %0;" :: "n"(N) : "memory")

// fused smem layout (bytes): pr ring (8 warps x 8 slots x 512B) + partials
#define FR_SLOT   512
#define FR_NSLOT  8
#define FR_RINGW  (FR_NSLOT * FR_SLOT)       // 4 KB / warp
#define FR_RING   (8 * FR_RINGW)             // 32 KB
#define FR_MB     (8 * 1160 * 4)             // 37120 B
#define FR_SMEM   (FR_RING + FR_MB + 64)     // 69952 B -> 2 CTAs = 139.9 KB/SM

// ---------------------------------------------------------------------------
// Kernel A: q/k/v projections. grid (128, 3), block 256 (8 warps).
// Block = 8 rows; warp = 4 rows x 32 cols (W slice/warp = 49 KB ->
// total W L2 traffic 150 MB). 384 blocks for latency hiding.
// ---------------------------------------------------------------------------
__global__ void __launch_bounds__(256) proj_kernel(
    const float* __restrict__ x,
    const float* __restrict__ Wq,
    const float* __restrict__ Wk,
    const float* __restrict__ Wv)
{
    __shared__ float xs[8 * DIMX];    // 12 KB
    const int rb = blockIdx.x * 8;
    const float* W   = (blockIdx.y == 0) ? Wq  : (blockIdx.y == 1) ? Wk  : Wv;
    float*       dst = (blockIdx.y == 0) ? g_q : (blockIdx.y == 1) ? g_k : g_v;
    const float scale = (blockIdx.y == 0) ? SCALAR_SCALE : 1.0f;

    for (int t = threadIdx.x; t < 8 * DIMX; t += 256)
        xs[t] = x[(size_t)rb * DIMX + t];
    __syncthreads();

    const int wid  = threadIdx.x >> 5;
    const int lane = threadIdx.x & 31;
    const int rg   = (wid >> 2) * 4;      // row group: 0 or 4 (4 rows each)
    const int cg   = wid & 3;             // col group: 0..3 (32 cols each)
    const int c    = cg * 32 + lane;

    float acc[4] = {0.f, 0.f, 0.f, 0.f};

    float wbuf[4];
#pragma unroll
    for (int u = 0; u < 4; u++)
        wbuf[u] = __ldg(&W[u * 128 + c]);

#pragma unroll 1
    for (int k0 = 0; k0 < DIMX; k0 += 4) {
        float wcur[4];
#pragma unroll
        for (int u = 0; u < 4; u++) wcur[u] = wbuf[u];
        const int kn = (k0 + 4 < DIMX) ? (k0 + 4) : 0;   // clamp: valid addr
#pragma unroll
        for (int u = 0; u < 4; u++)
            wbuf[u] = __ldg(&W[(kn + u) * 128 + c]);
#pragma unroll
        for (int u = 0; u < 4; u++) {
#pragma unroll
            for (int r = 0; r < 4; r++)
                acc[r] = fmaf(xs[(rg + r) * DIMX + k0 + u], wcur[u], acc[r]);
        }
    }
#pragma unroll
    for (int r = 0; r < 4; r++)
        dst[(size_t)(rb + rg + r) * 128 + c] = acc[r] * scale;
}

// ---------------------------------------------------------------------------
// Kernel B: FULLY FUSED single pass (v5: batch-4 two-phase). grid 1024
// (CTA = query i), block 256 (8 warps; warp = 128 consecutive j).
// 2 CTAs/SM -> 16 warps/SM. Lane = (h = lane&7, q = lane>>3).
//
// v5 change (from measured R16 serial-chain diagnosis): process j in BATCHES
// of 4. Phase 1: four logit chains (LDS pr -> dot -> 2 shfl -> exp) with
// pr TRANSIENT per j -> independent chains, ptxas interleaves (ILP), kills
// the ~135-cyc-per-j serialization. Phase 2: chain-free aggregation for the
// 4 j (pr re-read from still-live ring slots, p from regs). Ring halves
// (slots 0-3 / 4-7) ping-pong: one computes while the other loads
// (1 commit group per batch, CP_WAIT(1)).
// Registers: wb2 32 + accp 32 + p 4 + transients ~35 ~= 120 -> no spill.
// ---------------------------------------------------------------------------
__global__ void __launch_bounds__(256, 2) fused_kernel(
    const float* __restrict__ pair,
    const float* __restrict__ Wb,
    const float* __restrict__ bb,
    float* __restrict__ out)
{
    extern __shared__ char smem[];
    float* mb = (float*)(smem + FR_RING);    // 8 x 1160 partials
    float* rs = (float*)(smem + FR_RING + FR_MB);

    const int tid  = threadIdx.x;
    const int wid  = tid >> 5;
    const int lane = tid & 31;
    const int h    = lane & 7;
    const int q    = lane >> 3;

    const int i  = blockIdx.x;
    const int j0 = wid * 128;

    // Wb rows for this lane's d-set (chunks f = u*4+q), pre-scaled.
    u64 wb2[16];
#pragma unroll
    for (int u = 0; u < 8; u++) {
        const int d = (u * 4 + q) * 4;
        wb2[2 * u]     = pack2(Wb[(d + 0) * 8 + h] * PAIR_SCALE, Wb[(d + 1) * 8 + h] * PAIR_SCALE);
        wb2[2 * u + 1] = pack2(Wb[(d + 2) * 8 + h] * PAIR_SCALE, Wb[(d + 3) * 8 + h] * PAIR_SCALE);
    }
    const float4 qv = *(const float4*)&g_q[(size_t)i * 128 + h * 16 + q * 4];
    const float bbh = bb[h] * PAIR_SCALE;
    const int koff = h * 4 + q;      // float4 index of (h,q) slice in a row

    const float4* k4g = (const float4*)g_k;
    const float4* v4g = (const float4*)g_v;

    const char* prsrc = (const char*)pair + ((size_t)i * NN + j0) * 512;
    const int lb = lane * 16;
    const uint32_t ringw = smem_u32(smem) + wid * FR_RINGW;
    const char* ringp = smem + wid * FR_RINGW;

    u64 accp[16];
#pragma unroll
    for (int t = 0; t < 16; t++) accp[t] = 0ull;
    float4 accv = make_float4(0.f, 0.f, 0.f, 0.f);
    float l = 0.0f;

    // prologue: stage batch 0 (slots 0-3) and batch 1 (slots 4-7), one group each
#pragma unroll
    for (int b = 0; b < 2; b++) {
#pragma unroll
        for (int s = 0; s < 4; s++) {
            const int t = b * 4 + s;
            cp16_cg(ringw + t * FR_SLOT + lb, prsrc + (size_t)t * 512 + lb);
        }
        CP_COMMIT();
    }

#pragma unroll 1
    for (int tb = 0; tb < 32; tb++) {        // 32 batches of 4 j
        CP_WAIT(1);                          // current batch's half is ready
        __syncwarp();

        const int sbase = (tb & 1) * 4;      // slots of this batch
        const int t0 = tb * 4;

        // ---- phase 1: four independent logit chains ----
        float pv[4];
#pragma unroll
        for (int s = 0; s < 4; s++) {
            const float4* sp = (const float4*)(ringp + (sbase + s) * FR_SLOT);
            const float4 kc = __ldg(k4g + (size_t)(j0 + t0 + s) * 32 + koff);

            u64 a0 = 0ull, a1 = 0ull;
#pragma unroll
            for (int u = 0; u < 8; u++) {
                const float4 c = sp[u * 4 + q];
                a0 = ffma2(pack2(c.x, c.y), wb2[2 * u],     a0);
                a1 = ffma2(pack2(c.z, c.w), wb2[2 * u + 1], a1);
            }
            float d0, d1, d2, d3;
            unpack2(a0, d0, d1); unpack2(a1, d2, d3);

            float qk = qv.x * kc.x;
            qk = fmaf(qv.y, kc.y, qk);
            qk = fmaf(qv.z, kc.z, qk);
            qk = fmaf(qv.w, kc.w, qk);

            float dot = ((d0 + d1) + (d2 + d3)) + qk;
            dot += __shfl_xor_sync(0xffffffffu, dot, 8);
            dot += __shfl_xor_sync(0xffffffffu, dot, 16);
            pv[s] = __expf(dot + bbh);
        }

        // ---- phase 2: chain-free aggregation for the 4 j ----
#pragma unroll
        for (int s = 0; s < 4; s++) {
            const float4* sp = (const float4*)(ringp + (sbase + s) * FR_SLOT);
            const float4 vc = __ldg(v4g + (size_t)(j0 + t0 + s) * 32 + koff);
            const float p = pv[s];
            l += p;
            const u64 ph = pack2(p, p);
#pragma unroll
            for (int u = 0; u < 8; u++) {
                const float4 c = sp[u * 4 + q];
                accp[2 * u]     = ffma2(ph, pack2(c.x, c.y), accp[2 * u]);
                accp[2 * u + 1] = ffma2(ph, pack2(c.z, c.w), accp[2 * u + 1]);
            }
            accv.x = fmaf(p, vc.x, accv.x);
            accv.y = fmaf(p, vc.y, accv.y);
            accv.z = fmaf(p, vc.z, accv.z);
            accv.w = fmaf(p, vc.w, accv.w);
        }

        __syncwarp();                        // all lanes done with this half

        // refill this half with rows t0+8..t0+11 (wrapped valid addrs)
#pragma unroll
        for (int s = 0; s < 4; s++) {
            const int tr = (t0 + 8 + s) & 127;
            cp16_cg(ringw + (sbase + s) * FR_SLOT + lb, prsrc + (size_t)tr * 512 + lb);
        }
        CP_COMMIT();
    }
    CP_WAIT(0);

    // ---- epilogue: dump per-warp partials, reduce across 8 warps ----
    {
        float* m = mb + wid * 1160;
        *(float4*)&m[koff * 4] = accv;                    // v part: h*16 + q*4
#pragma unroll
        for (int u = 0; u < 8; u++) {
            float a0, a1, a2, a3;
            unpack2(accp[2 * u],     a0, a1);
            unpack2(accp[2 * u + 1], a2, a3);
            *(float4*)&m[128 + h * 128 + u * 16 + q * 4] = make_float4(a0, a1, a2, a3);
        }
        if (q == 0) m[1152 + h] = l;
    }
    __syncthreads();

    if (tid < 8) {
        float s = 0.0f;
#pragma unroll
        for (int w = 0; w < 8; w++) s += mb[w * 1160 + 1152 + tid];
        rs[tid] = 1.0f / s;
    }
    __syncthreads();

    const size_t ob = (size_t)i * OUTW;
    for (int idx = tid; idx < OUTW; idx += 256) {
        float s = 0.0f;
#pragma unroll
        for (int w = 0; w < 8; w++) s += mb[w * 1160 + idx];
        const int head = (idx < 128) ? (idx >> 4) : ((idx - 128) >> 7);
        out[ob + idx] = s * rs[head];
    }
}

// ---------------------------------------------------------------------------
extern "C" void kernel_launch(void* const* d_in, const int* in_sizes, int n_in,
                              void* d_out, int out_size)
{
    (void)in_sizes; (void)n_in; (void)out_size;
    const float* x    = (const float*)d_in[0];
    const float* pair = (const float*)d_in[1];
    // d_in[2]=rotations, d_in[3]=translations, d_in[4]=mask: unused by reference math
    const float* Wq = (const float*)d_in[5];
    const float* Wk = (const float*)d_in[6];
    const float* Wv = (const float*)d_in[7];
    const float* Wb = (const float*)d_in[8];
    const float* bb = (const float*)d_in[9];
    float* out = (float*)d_out;

    proj_kernel<<<dim3(128, 3, 1), 256>>>(x, Wq, Wk, Wv);

    cudaFuncSetAttribute(fused_kernel, cudaFuncAttributeMaxDynamicSharedMemorySize, FR_SMEM);
    fused_kernel<<<1024, 256, FR_SMEM>>>(pair, Wb, bb, out);
}